// round 17
// baseline (speedup 1.0000x reference)
#include <cuda_runtime.h>
#include <cuda_fp16.h>

#define NN 100000
#define H1D 4
#define CD 8
#define NEG 0.2f

// Persistent device scratch (no allocations allowed in kernel_launch).
// Zero-initialized at module load; k_mid restores g_acc1's zero invariant
// after consuming it and lazily initializes g_acc2 each call.
__device__ float g_acc1[NN * 8];    // per node: S0,T0,S1,T1,S2,T2,S3,T3 (32B aligned)
__device__ float g_acc2[NN * 12];   // per node: S, num[0..7], pad x3 (48B, 16B-aligned)

// Packed layer-2 source record: h2 fp16x8 (16B) + als fp32 => 20B in 32B record
struct __align__(32) Node2 {
    __half2 h2[4];
    float   als;
    float   pad[3];
};
__device__ Node2 g_n2[NN];
__device__ float g_ald[NN];         // dense read-only during edge2 (L1-cacheable)

__device__ __forceinline__ void red4(float* addr, float a, float b, float c, float d) {
    asm volatile("red.global.add.v4.f32 [%0], {%1, %2, %3, %4};"
                 :: "l"(addr), "f"(a), "f"(b), "f"(c), "f"(d) : "memory");
}

// Compute per-head logit scalars ws/wd into shared memory (threads 0..3).
__device__ __forceinline__ void prep_wswd(float* sws, float* swd,
                                          const float* __restrict__ W1,
                                          const float* __restrict__ as1,
                                          const float* __restrict__ ad1) {
    int tid = threadIdx.x;
    if (tid < H1D) {
        float s = 0.0f, d = 0.0f;
#pragma unroll
        for (int c = 0; c < CD; c++) {
            float w = W1[tid * CD + c];
            s += w * as1[tid * CD + c];
            d += w * ad1[tid * CD + c];
        }
        sws[tid] = s;
        swd[tid] = d;
    }
}

// ---------------------------------------------------------------------------
// 1) layer-1 edge pass (real edges only), 2 edges per thread (int2 indices):
//    per head: w = exp(lrelu(x_s*ws + x_d*wd)); acc1[dst] += {S_h: w, T_h: w*x_s}
// ---------------------------------------------------------------------------
__device__ __forceinline__ void edge1_body(const float* __restrict__ x,
                                           const float* sws, const float* swd,
                                           int s, int d) {
    float xs = __ldg(&x[s]);
    float xd = __ldg(&x[d]);
    float v[8];
#pragma unroll
    for (int h = 0; h < H1D; h++) {
        float e = xs * sws[h] + xd * swd[h];
        e = (e > 0.0f) ? e : NEG * e;
        float w = __expf(e);
        v[2 * h]     = w;
        v[2 * h + 1] = w * xs;
    }
    float* base = &g_acc1[(size_t)d * 8];
    red4(base,     v[0], v[1], v[2], v[3]);
    red4(base + 4, v[4], v[5], v[6], v[7]);
}

__global__ void __launch_bounds__(256) k_edge1(const float* __restrict__ x,
                                               const int* __restrict__ src,
                                               const int* __restrict__ dst,
                                               const float* __restrict__ W1,
                                               const float* __restrict__ as1,
                                               const float* __restrict__ ad1,
                                               int E) {
    __shared__ float sws[H1D], swd[H1D];
    prep_wswd(sws, swd, W1, as1, ad1);
    __syncthreads();

    int t = blockIdx.x * blockDim.x + threadIdx.x;
    int i0 = 2 * t;
    if (i0 >= E) return;
    if (i0 + 1 < E) {
        int2 ss = *reinterpret_cast<const int2*>(src + i0);
        int2 dd = *reinterpret_cast<const int2*>(dst + i0);
        edge1_body(x, sws, swd, ss.x, dd.x);
        edge1_body(x, sws, swd, ss.y, dd.y);
    } else {
        edge1_body(x, sws, swd, src[i0], dst[i0]);
    }
}

// ---------------------------------------------------------------------------
// 2) per-node: layer-1 self-loop + epilogue + relu + W2 GEMV + layer-2 logit
//    precompute. Writes packed source record + dense ald, zero-inits g_acc2,
//    and restores g_acc1's zero invariant.
// ---------------------------------------------------------------------------
__global__ void __launch_bounds__(256) k_mid(const float* __restrict__ x,
                                             const float* __restrict__ W1,
                                             const float* __restrict__ as1,
                                             const float* __restrict__ ad1,
                                             const float* __restrict__ b1,
                                             const float* __restrict__ W2,
                                             const float* __restrict__ as2,
                                             const float* __restrict__ ad2) {
    __shared__ float sW2[32 * 8];
    __shared__ float sW1[32];
    __shared__ float sb1[32];
    __shared__ float sa[16];
    __shared__ float sws[H1D], swd[H1D];
    int tid = threadIdx.x;
    prep_wswd(sws, swd, W1, as1, ad1);
    if (tid < 256) sW2[tid] = W2[tid];
    if (tid < 32) { sW1[tid] = W1[tid]; sb1[tid] = b1[tid]; }
    if (tid < 8)  { sa[tid] = as2[tid]; sa[8 + tid] = ad2[tid]; }
    __syncthreads();

    int n = blockIdx.x * blockDim.x + tid;
    if (n >= NN) return;

    float4* a1 = reinterpret_cast<float4*>(&g_acc1[(size_t)n * 8]);
    float4 p0 = a1[0];  // S0,T0,S1,T1
    float4 p1 = a1[1];  // S2,T2,S3,T3

    // restore zero invariant for the next kernel_launch call
    float4 z = make_float4(0.f, 0.f, 0.f, 0.f);
    a1[0] = z;
    a1[1] = z;

    // layer-1 self-loop contribution (src = dst = n)
    float xd = __ldg(&x[n]);
    float Sv[H1D] = {p0.x, p0.z, p1.x, p1.z};
    float Tv[H1D] = {p0.y, p0.w, p1.y, p1.w};
#pragma unroll
    for (int h = 0; h < H1D; h++) {
        float e = xd * (sws[h] + swd[h]);
        e = (e > 0.0f) ? e : NEG * e;
        float w = __expf(e);
        Sv[h] += w;
        Tv[h] += w * xd;
    }

    float ts[H1D];
#pragma unroll
    for (int h = 0; h < H1D; h++) ts[h] = Tv[h] / Sv[h];

    float h2[CD];
#pragma unroll
    for (int c = 0; c < CD; c++) h2[c] = 0.0f;
#pragma unroll
    for (int hc = 0; hc < 32; hc++) {
        float r = sW1[hc] * ts[hc >> 3] + sb1[hc];
        r = fmaxf(r, 0.0f);
#pragma unroll
        for (int c = 0; c < CD; c++) h2[c] += r * sW2[hc * 8 + c];
    }
    float als = 0.0f, ald = 0.0f;
#pragma unroll
    for (int c = 0; c < CD; c++) {
        als += h2[c] * sa[c];
        ald += h2[c] * sa[8 + c];
    }

    // pack h2 -> fp16x8 (one 16B store) + als
    __half2 pk[4];
    pk[0] = __floats2half2_rn(h2[0], h2[1]);
    pk[1] = __floats2half2_rn(h2[2], h2[3]);
    pk[2] = __floats2half2_rn(h2[4], h2[5]);
    pk[3] = __floats2half2_rn(h2[6], h2[7]);
    *reinterpret_cast<uint4*>(g_n2[n].h2) = *reinterpret_cast<const uint4*>(pk);
    g_n2[n].als = als;
    g_ald[n] = ald;

    // lazy zero-init of this node's layer-2 accumulator record (used by edge2)
    float* ab = &g_acc2[(size_t)n * 12];
    reinterpret_cast<float4*>(ab)[0] = z;
    reinterpret_cast<float4*>(ab)[1] = z;
    ab[8] = 0.0f;
}

// ---------------------------------------------------------------------------
// 3) layer-2 edge pass (real edges only), 2 edges per thread:
//    w = exp(lrelu(als[s] + ald[d])); acc2[d] += {S: w, num[c]: w*h2[s][c]}
// ---------------------------------------------------------------------------
__device__ __forceinline__ void edge2_body(int s, int d) {
    uint4 raw = *reinterpret_cast<const uint4*>(g_n2[s].h2);
    __half2 pk[4];
    *reinterpret_cast<uint4*>(pk) = raw;
    float als = g_n2[s].als;
    float ald = __ldg(&g_ald[d]);

    float e = als + ald;
    e = (e > 0.0f) ? e : NEG * e;
    float w = __expf(e);

    float2 f0 = __half22float2(pk[0]);
    float2 f1 = __half22float2(pk[1]);
    float2 f2 = __half22float2(pk[2]);
    float2 f3 = __half22float2(pk[3]);

    float* ab = &g_acc2[(size_t)d * 12];
    red4(ab,     w,        w * f0.x, w * f0.y, w * f1.x);
    red4(ab + 4, w * f1.y, w * f2.x, w * f2.y, w * f3.x);
    atomicAdd(ab + 8, w * f3.y);
}

__global__ void __launch_bounds__(256) k_edge2(const int* __restrict__ src,
                                               const int* __restrict__ dst,
                                               int E) {
    int t = blockIdx.x * blockDim.x + threadIdx.x;
    int i0 = 2 * t;
    if (i0 >= E) return;
    if (i0 + 1 < E) {
        int2 ss = *reinterpret_cast<const int2*>(src + i0);
        int2 dd = *reinterpret_cast<const int2*>(dst + i0);
        edge2_body(ss.x, dd.x);
        edge2_body(ss.y, dd.y);
    } else {
        edge2_body(src[i0], dst[i0]);
    }
}

// ---------------------------------------------------------------------------
// 4) final: layer-2 self-loop analytically, normalize + bias -> out.
//    2 threads per node, all record loads 16B-aligned vectors:
//      half0 loads A=(S,n0,n1,n2)@+0;  half1 loads B=(n3..n6)@+16, D=(n7..)@+32
//    one shfl_xor(1) pair exchanges S <-> n3.
// ---------------------------------------------------------------------------
__global__ void __launch_bounds__(256) k_final(float* __restrict__ out,
                                               const float* __restrict__ b2) {
    __shared__ float sb2[8];
    int tid = threadIdx.x;
    if (tid < 8) sb2[tid] = b2[tid];
    __syncthreads();

    int t = blockIdx.x * blockDim.x + tid;
    int n = t >> 1;
    int half = t & 1;
    if (n >= NN) return;

    const float* ab = &g_acc2[(size_t)n * 12];
    float4 v;      // this half's 4 numerator values n[4*half .. 4*half+3]
    float S;       // denominator accumulator (real edges)
    if (half == 0) {
        float4 A = reinterpret_cast<const float4*>(ab)[0];      // S,n0,n1,n2
        S = A.x;
        v = make_float4(A.y, A.z, A.w, 0.0f);                   // n3 via shuffle
    } else {
        float4 B = reinterpret_cast<const float4*>(ab)[1];      // n3,n4,n5,n6
        float4 D = reinterpret_cast<const float4*>(ab)[2];      // n7,pad...
        S = B.x;                                                // carries n3 for partner
        v = make_float4(B.y, B.z, B.w, D.x);                    // n4,n5,n6,n7
    }
    // exchange: half0 receives n3 (partner's S slot), half1 receives S
    float ex = __shfl_xor_sync(0xffffffffu, S, 1);
    if (half == 0) { v.w = ex; }            // n3
    else           { S = ex; }              // real S

    // this half's h2 channels (8B packed fp16) + full logits
    const __half2* hp = g_n2[n].h2 + half * 2;
    __half2 pa = hp[0];
    __half2 pb = hp[1];
    float als = g_n2[n].als;
    float ald = g_ald[n];

    float e = als + ald;
    e = (e > 0.0f) ? e : NEG * e;
    float w = __expf(e);

    float2 fa = __half22float2(pa);
    float2 fb = __half22float2(pb);

    float inv = 1.0f / ((half == 0 ? S : ex) + w);
    // note: for half0 S already holds the denominator accumulator
    const float* bb = &sb2[half * 4];
    float4 o = make_float4((v.x + w * fa.x) * inv + bb[0],
                           (v.y + w * fa.y) * inv + bb[1],
                           (v.z + w * fb.x) * inv + bb[2],
                           (v.w + w * fb.y) * inv + bb[3]);
    reinterpret_cast<float4*>(&out[(size_t)n * 8])[half] = o;
}

extern "C" void kernel_launch(void* const* d_in, const int* in_sizes, int n_in,
                              void* d_out, int out_size) {
    const float* x   = (const float*)d_in[0];
    const int*   ei  = (const int*)d_in[1];
    const float* W1  = (const float*)d_in[2];
    const float* as1 = (const float*)d_in[3];
    const float* ad1 = (const float*)d_in[4];
    const float* b1  = (const float*)d_in[5];
    const float* W2  = (const float*)d_in[6];
    const float* as2 = (const float*)d_in[7];
    const float* ad2 = (const float*)d_in[8];
    const float* b2  = (const float*)d_in[9];
    float* out = (float*)d_out;

    int E = in_sizes[1] / 2;
    const int* src = ei;
    const int* dst = ei + E;

    int tb = 256;
    int eb2 = ((E + 1) / 2 + tb - 1) / tb;   // 2 edges per thread
    int nb = (NN + tb - 1) / tb;
    int nb2 = (NN * 2 + tb - 1) / tb;        // 2 threads per node

    k_edge1<<<eb2, tb>>>(x, src, dst, W1, as1, ad1, E);
    k_mid<<<nb, tb>>>(x, W1, as1, ad1, b1, W2, as2, ad2);
    k_edge2<<<eb2, tb>>>(src, dst, E);
    k_final<<<nb2, tb>>>(out, b2);
}